// round 6
// baseline (speedup 1.0000x reference)
#include <cuda_runtime.h>

#define HH 1024
#define WW 1024
#define HWSZ (HH * WW)

typedef unsigned long long u64;

// Scratch: ping-pong h/c state + decoder h scratch.
__device__ float g_h[2][HWSZ];
__device__ float g_c[2][HWSZ];
__device__ float g_x[HWSZ];

// Prep-kernel output: prescaled, pair-duplicated weights/bias.
__device__ u64 g_wpack[2][72];
__device__ u64 g_bpack[2][4];

// [0] = encoder, [1] = decoder. Each u64 = {w,w} (f32x2), prescaled:
// gates i,f,o by -log2(e); gate g by -2*log2(e).
__constant__ u64 c_w2[2][72];
__constant__ u64 c_b2[2][4];

__device__ __forceinline__ u64 pk(float lo, float hi) {
    u64 r; asm("mov.b64 %0, {%1, %2};" : "=l"(r) : "f"(lo), "f"(hi)); return r;
}
__device__ __forceinline__ void upk(u64 v, float& lo, float& hi) {
    asm("mov.b64 {%0, %1}, %2;" : "=f"(lo), "=f"(hi) : "l"(v));
}
__device__ __forceinline__ u64 fma2(u64 a, u64 b, u64 c) {
    u64 d; asm("fma.rn.f32x2 %0, %1, %2, %3;" : "=l"(d) : "l"(a), "l"(b), "l"(c));
    return d;
}
__device__ __forceinline__ float ex2f(float x) {
    float r; asm("ex2.approx.f32 %0, %1;" : "=f"(r) : "f"(x)); return r;
}
__device__ __forceinline__ float rcpf(float x) {
    float r; asm("rcp.approx.f32 %0, %1;" : "=f"(r) : "f"(x)); return r;
}

// Build prescaled packed weights/bias from raw device weights.
__global__ void prep_kernel(const float* __restrict__ ew, const float* __restrict__ eb,
                            const float* __restrict__ dw, const float* __restrict__ db)
{
    int t = threadIdx.x;
    if (t < 144) {
        int ws = t / 72, k = t % 72, g = k / 18;
        float s = (g == 3) ? -2.885390082f : -1.442695041f;
        float v = (ws ? dw : ew)[k] * s;
        g_wpack[ws][k] = pk(v, v);
    } else if (t < 152) {
        int ws = (t - 144) / 4, g = (t - 144) % 4;
        float s = (g == 3) ? -2.885390082f : -1.442695041f;
        float v = (ws ? db : eb)[g] * s;
        g_bpack[ws][g] = pk(v, v);
    }
}

// Fused ConvLSTM step. Prescaled gates: sigmoid(v) = rcp(1+ex2(acc)),
// tanh(v) = 2*rcp(1+ex2(acc_g)) - 1 with the scale folded into weights.
// Pixels packed as strided f32x2 pairs (px0,px2)/(px1,px3) for FFMA2 conv.
template <int WS, bool FIRST, bool ENC>
__global__ __launch_bounds__(256) void step_kernel(
    const float* __restrict__ xbase,
    const float* __restrict__ h_in,
    const float* __restrict__ c_in,
    float* __restrict__ h_out,
    float* __restrict__ c_out,
    const int* __restrict__ p_epoch,
    const int* __restrict__ p_lim,
    int s)
{
    const int x0 = (blockIdx.x * blockDim.x + threadIdx.x) * 4;
    const int y  = blockIdx.y * blockDim.y + threadIdx.y;
    const size_t base = (size_t)y * WW + x0;

    int frame = s;
    if (ENC) frame += p_epoch[0];
    if (frame >= p_lim[0]) {
        // Inactive step: pass state through unchanged (graph-shape invariant).
        float4 hz, cz;
        if (FIRST) {
            hz = make_float4(0.f, 0.f, 0.f, 0.f); cz = hz;
        } else {
            hz = *(const float4*)(h_in + base);
            cz = *(const float4*)(c_in + base);
        }
        *(float4*)(h_out + base) = hz;
        *(float4*)(c_out + base) = cz;
        return;
    }

    const float* xp = ENC ? (xbase + (size_t)frame * HWSZ) : xbase;

    // Packed strided neighborhoods: XP[dy] = {v0,v2},{v1,v3},{v2,v4},{v3,v5}
    // where v0=left, v1..v4=center float4, v5=right (SAME zero padding).
    u64 XP[3][4];
    u64 HP[3][4];
#pragma unroll
    for (int dy = 0; dy < 3; dy++) {
        const int r = y + dy - 1;
        const bool rv = ((unsigned)r < HH);
        const size_t ro = (size_t)r * WW;

        float4 mx = make_float4(0.f, 0.f, 0.f, 0.f);
        float lx = 0.f, rx = 0.f;
        if (rv) {
            mx = *(const float4*)(xp + ro + x0);
            if (x0 > 0)      lx = xp[ro + x0 - 1];
            if (x0 + 4 < WW) rx = xp[ro + x0 + 4];
        }
        XP[dy][0] = pk(lx,   mx.y);
        XP[dy][1] = pk(mx.x, mx.z);
        XP[dy][2] = pk(mx.y, mx.w);
        XP[dy][3] = pk(mx.z, rx);

        if (!FIRST) {
            float4 mh = make_float4(0.f, 0.f, 0.f, 0.f);
            float lh = 0.f, rh = 0.f;
            if (rv) {
                mh = *(const float4*)(h_in + ro + x0);
                if (x0 > 0)      lh = h_in[ro + x0 - 1];
                if (x0 + 4 < WW) rh = h_in[ro + x0 + 4];
            }
            HP[dy][0] = pk(lh,   mh.y);
            HP[dy][1] = pk(mh.x, mh.z);
            HP[dy][2] = pk(mh.y, mh.w);
            HP[dy][3] = pk(mh.z, rh);
        }
    }

    // accE[g] = gates for (px0,px2); accO[g] = gates for (px1,px3).
    u64 accE[4], accO[4];
#pragma unroll
    for (int g = 0; g < 4; g++) {
        const u64 b = c_b2[WS][g];
        accE[g] = b; accO[g] = b;
    }

#pragma unroll
    for (int dy = 0; dy < 3; dy++) {
#pragma unroll
        for (int g = 0; g < 4; g++) {
#pragma unroll
            for (int dx = 0; dx < 3; dx++) {
                const u64 wx = c_w2[WS][g * 18 + dy * 3 + dx];
                accE[g] = fma2(XP[dy][dx],     wx, accE[g]);
                accO[g] = fma2(XP[dy][dx + 1], wx, accO[g]);
                if (!FIRST) {
                    const u64 wh = c_w2[WS][g * 18 + 9 + dy * 3 + dx];
                    accE[g] = fma2(HP[dy][dx],     wh, accE[g]);
                    accO[g] = fma2(HP[dy][dx + 1], wh, accO[g]);
                }
            }
        }
    }

    float a[4][4];
#pragma unroll
    for (int g = 0; g < 4; g++) {
        upk(accE[g], a[0][g], a[2][g]);
        upk(accO[g], a[1][g], a[3][g]);
    }

    float cp[4] = {0.f, 0.f, 0.f, 0.f};
    if (!FIRST) {
        const float4 cc = *(const float4*)(c_in + base);
        cp[0] = cc.x; cp[1] = cc.y; cp[2] = cc.z; cp[3] = cc.w;
    }

    float hn[4], cn[4];
#pragma unroll
    for (int j = 0; j < 4; j++) {
        const float ig = rcpf(1.f + ex2f(a[j][0]));
        const float fg = rcpf(1.f + ex2f(a[j][1]));
        const float og = rcpf(1.f + ex2f(a[j][2]));
        const float gg = fmaf(rcpf(1.f + ex2f(a[j][3])), 2.f, -1.f);
        const float c2 = FIRST ? (ig * gg) : fmaf(fg, cp[j], ig * gg);
        cn[j] = c2;
        const float t = fmaf(rcpf(1.f + ex2f(c2 * -2.885390082f)), 2.f, -1.f);
        hn[j] = og * t;
    }
    *(float4*)(h_out + base) = make_float4(hn[0], hn[1], hn[2], hn[3]);
    *(float4*)(c_out + base) = make_float4(cn[0], cn[1], cn[2], cn[3]);
}

extern "C" void kernel_launch(void* const* d_in, const int* in_sizes, int n_in,
                              void* d_out, int out_size)
{
    const float* data  = (const float*)d_in[0];   // [20,1,1,1024,1024]
    const float* enc_w = (const float*)d_in[1];   // [4,2,3,3]
    const float* enc_b = (const float*)d_in[2];   // [4]
    const float* dec_w = (const float*)d_in[3];   // [4,2,3,3]
    const float* dec_b = (const float*)d_in[4];   // [4]
    const int*   epoch = (const int*)d_in[5];
    const int*   t_en  = (const int*)d_in[6];
    const int*   t_de  = (const int*)d_in[7];
    float*       out   = (float*)d_out;           // [1024,1024]

    // Build prescaled/packed weights, then stage into constant bank.
    prep_kernel<<<1, 160>>>(enc_w, enc_b, dec_w, dec_b);
    void *wp = nullptr, *bp = nullptr;
    cudaGetSymbolAddress(&wp, g_wpack);
    cudaGetSymbolAddress(&bp, g_bpack);
    cudaMemcpyToSymbolAsync(c_w2, wp, sizeof(u64) * 2 * 72, 0,
                            cudaMemcpyDeviceToDevice, 0);
    cudaMemcpyToSymbolAsync(c_b2, bp, sizeof(u64) * 2 * 4, 0,
                            cudaMemcpyDeviceToDevice, 0);

    float *hbuf = nullptr, *cbuf = nullptr, *xdec = nullptr;
    cudaGetSymbolAddress((void**)&hbuf, g_h);
    cudaGetSymbolAddress((void**)&cbuf, g_c);
    cudaGetSymbolAddress((void**)&xdec, g_x);
    float* hA = hbuf;  float* hB = hbuf + HWSZ;
    float* cA = cbuf;  float* cB = cbuf + HWSZ;

    const dim3 blk(64, 4);
    const dim3 grd(WW / 256, HH / 4);   // (4, 256)

    // ---- Encoder: 20 steps over data[epoch + s], active while frame < T_en ----
    step_kernel<0, true, true><<<grd, blk>>>(data, hA, cA, hB, cB, epoch, t_en, 0);
    for (int s = 1; s < 20; s++) {
        float* hi = (s & 1) ? hB : hA;
        float* ho = (s & 1) ? hA : hB;
        float* ci = (s & 1) ? cB : cA;
        float* co = (s & 1) ? cA : cB;
        step_kernel<0, false, true><<<grd, blk>>>(data, hi, ci, ho, co, epoch, t_en, s);
    }
    // Final encoder h lives in hA (s=19 odd) and stays untouched below:
    // the decoder reads it directly as its constant input x.

    // ---- Decoder: 20 steps, x = hA, h ping-pongs g_x <-> d_out (final -> d_out) ----
    step_kernel<1, true, false><<<grd, blk>>>(hA, xdec, cB, xdec, cA, epoch, t_de, 0);
    for (int s = 1; s < 20; s++) {
        float* hi = (s & 1) ? xdec : out;
        float* ho = (s & 1) ? out  : xdec;
        float* ci = (s & 1) ? cA : cB;
        float* co = (s & 1) ? cB : cA;
        step_kernel<1, false, false><<<grd, blk>>>(hA, hi, ci, ho, co, epoch, t_de, s);
    }
    // s=19 (odd) wrote h to d_out. Done — no final copy needed.
}

// round 7
// speedup vs baseline: 1.2480x; 1.2480x over previous
#include <cuda_runtime.h>

#define HH 1024
#define WW 1024
#define HWSZ (HH * WW)
#define YSPLIT 512   // each thread does rows y and y+YSPLIT -> 512-block grid, 1 wave

// Scratch: encoder ping-pong h/c, decoder h scratch, precomputed decoder x-gates.
__device__ float  g_h[2][HWSZ];
__device__ float  g_c[2][HWSZ];
__device__ float  g_x[HWSZ];
__device__ float4 g_gx[HWSZ];   // per-pixel (i,f,o,g) pre-activations from x + bias

// Prep output + constant bank. Weights prescaled for the tanh-form activations:
// gates i,f,o scaled by 0.5 (sigmoid(v) = 0.5 + 0.5*tanh(0.5 v)); gate g unscaled.
__device__   float g_wpack[2][72];
__device__   float g_bpack[2][4];
__constant__ float c_w[2][72];
__constant__ float c_b[2][4];

__device__ __forceinline__ float tanhx(float x) {
    float r; asm("tanh.approx.f32 %0, %1;" : "=f"(r) : "f"(x)); return r;
}

__global__ void prep_kernel(const float* __restrict__ ew, const float* __restrict__ eb,
                            const float* __restrict__ dw, const float* __restrict__ db)
{
    int t = threadIdx.x;
    if (t < 144) {
        int ws = t / 72, k = t % 72, g = k / 18;
        float s = (g == 3) ? 1.0f : 0.5f;
        g_wpack[ws][k] = (ws ? dw : ew)[k] * s;
    } else if (t < 152) {
        int ws = (t - 144) / 4, g = (t - 144) % 4;
        float s = (g == 3) ? 1.0f : 0.5f;
        g_bpack[ws][g] = (ws ? db : eb)[g] * s;
    }
}

// Load a 3x6 neighborhood (SAME zero padding) for 4 horizontally adjacent pixels.
__device__ __forceinline__ void load_nbhd(const float* __restrict__ p, int y, int x0,
                                          bool hasL, bool hasR, float v[3][6])
{
#pragma unroll
    for (int dy = 0; dy < 3; dy++) {
        const int r = y + dy - 1;
        const bool rv = ((unsigned)r < HH);
        const size_t ro = (size_t)r * WW;
        float4 m = make_float4(0.f, 0.f, 0.f, 0.f);
        float l = 0.f, rr = 0.f;
        if (rv) {
            m = *(const float4*)(p + ro + x0);
            if (hasL) l  = p[ro + x0 - 1];
            if (hasR) rr = p[ro + x0 + 4];
        }
        v[dy][0] = l;   v[dy][1] = m.x; v[dy][2] = m.y;
        v[dy][3] = m.z; v[dy][4] = m.w; v[dy][5] = rr;
    }
}

// ---------------- Encoder step: full conv(concat(x,h)) + LSTM update ----------------
template <bool FIRST>
__global__ __launch_bounds__(256) void enc_step(
    const float* __restrict__ data,
    const float* __restrict__ h_in, const float* __restrict__ c_in,
    float* __restrict__ h_out, float* __restrict__ c_out,
    const int* __restrict__ p_epoch, const int* __restrict__ p_lim, int s)
{
    const int x0 = (blockIdx.x * blockDim.x + threadIdx.x) * 4;
    const int y0 = blockIdx.y * blockDim.y + threadIdx.y;
    const bool hasL = x0 > 0, hasR = x0 + 4 < WW;
    const int frame = p_epoch[0] + s;
    const bool active = frame < p_lim[0];
    const float* xp = data + (size_t)frame * HWSZ;

#pragma unroll
    for (int half = 0; half < 2; half++) {
        const int y = y0 + half * YSPLIT;
        const size_t base = (size_t)y * WW + x0;

        if (!active) {  // pass state through: launch count stays input-independent
            float4 hz, cz;
            if (FIRST) { hz = make_float4(0.f,0.f,0.f,0.f); cz = hz; }
            else { hz = *(const float4*)(h_in + base); cz = *(const float4*)(c_in + base); }
            *(float4*)(h_out + base) = hz;
            *(float4*)(c_out + base) = cz;
            continue;
        }

        float xv[3][6], hv[3][6];
        load_nbhd(xp, y, x0, hasL, hasR, xv);
        if (!FIRST) load_nbhd(h_in, y, x0, hasL, hasR, hv);

        float acc[4][4];
#pragma unroll
        for (int j = 0; j < 4; j++)
#pragma unroll
            for (int g = 0; g < 4; g++) acc[j][g] = c_b[0][g];

#pragma unroll
        for (int dy = 0; dy < 3; dy++) {
#pragma unroll
            for (int dx = 0; dx < 3; dx++) {
#pragma unroll
                for (int g = 0; g < 4; g++) {
                    const float wx = c_w[0][g * 18 + dy * 3 + dx];
#pragma unroll
                    for (int j = 0; j < 4; j++) acc[j][g] += wx * xv[dy][j + dx];
                }
                if (!FIRST) {
#pragma unroll
                    for (int g = 0; g < 4; g++) {
                        const float wh = c_w[0][g * 18 + 9 + dy * 3 + dx];
#pragma unroll
                        for (int j = 0; j < 4; j++) acc[j][g] += wh * hv[dy][j + dx];
                    }
                }
            }
        }

        float cp[4] = {0.f, 0.f, 0.f, 0.f};
        if (!FIRST) {
            const float4 cc = *(const float4*)(c_in + base);
            cp[0] = cc.x; cp[1] = cc.y; cp[2] = cc.z; cp[3] = cc.w;
        }

        float hn[4], cn[4];
#pragma unroll
        for (int j = 0; j < 4; j++) {
            const float ig = fmaf(tanhx(acc[j][0]), 0.5f, 0.5f);
            const float og = fmaf(tanhx(acc[j][2]), 0.5f, 0.5f);
            const float gg = tanhx(acc[j][3]);
            float c2;
            if (FIRST) c2 = ig * gg;
            else {
                const float fg = fmaf(tanhx(acc[j][1]), 0.5f, 0.5f);
                c2 = fmaf(fg, cp[j], ig * gg);
            }
            cn[j] = c2;
            hn[j] = og * tanhx(c2);
        }
        *(float4*)(h_out + base) = make_float4(hn[0], hn[1], hn[2], hn[3]);
        *(float4*)(c_out + base) = make_float4(cn[0], cn[1], cn[2], cn[3]);
    }
}

// ------- Decoder x-gates precompute: gx = conv_wx(x_dec) + b (prescaled) -------
__global__ __launch_bounds__(256) void gx_kernel(const float* __restrict__ xin)
{
    const int x0 = (blockIdx.x * blockDim.x + threadIdx.x) * 4;
    const int y0 = blockIdx.y * blockDim.y + threadIdx.y;
    const bool hasL = x0 > 0, hasR = x0 + 4 < WW;

#pragma unroll
    for (int half = 0; half < 2; half++) {
        const int y = y0 + half * YSPLIT;
        const size_t base = (size_t)y * WW + x0;

        float xv[3][6];
        load_nbhd(xin, y, x0, hasL, hasR, xv);

        float acc[4][4];
#pragma unroll
        for (int j = 0; j < 4; j++)
#pragma unroll
            for (int g = 0; g < 4; g++) acc[j][g] = c_b[1][g];

#pragma unroll
        for (int dy = 0; dy < 3; dy++)
#pragma unroll
            for (int dx = 0; dx < 3; dx++)
#pragma unroll
                for (int g = 0; g < 4; g++) {
                    const float wx = c_w[1][g * 18 + dy * 3 + dx];
#pragma unroll
                    for (int j = 0; j < 4; j++) acc[j][g] += wx * xv[dy][j + dx];
                }

#pragma unroll
        for (int j = 0; j < 4; j++)
            g_gx[base + j] = make_float4(acc[j][0], acc[j][1], acc[j][2], acc[j][3]);
    }
}

// ------- Decoder step 0: h=c=0, gates come straight from g_gx (pointwise) -------
__global__ __launch_bounds__(256) void dec_first(
    float* __restrict__ h_out, float* __restrict__ c_out,
    const int* __restrict__ p_lim)
{
    const int x0 = (blockIdx.x * blockDim.x + threadIdx.x) * 4;
    const int y0 = blockIdx.y * blockDim.y + threadIdx.y;
    const bool active = 0 < p_lim[0];

#pragma unroll
    for (int half = 0; half < 2; half++) {
        const size_t base = (size_t)(y0 + half * YSPLIT) * WW + x0;
        float hn[4], cn[4];
#pragma unroll
        for (int j = 0; j < 4; j++) {
            if (active) {
                const float4 gv = g_gx[base + j];
                const float ig = fmaf(tanhx(gv.x), 0.5f, 0.5f);
                const float og = fmaf(tanhx(gv.z), 0.5f, 0.5f);
                const float gg = tanhx(gv.w);
                const float c2 = ig * gg;
                cn[j] = c2;
                hn[j] = og * tanhx(c2);
            } else { hn[j] = 0.f; cn[j] = 0.f; }
        }
        *(float4*)(h_out + base) = make_float4(hn[0], hn[1], hn[2], hn[3]);
        *(float4*)(c_out + base) = make_float4(cn[0], cn[1], cn[2], cn[3]);
    }
}

// ------- Decoder step s>=1: only the h-half conv; x-half read from g_gx -------
__global__ __launch_bounds__(256) void dec_step(
    const float* __restrict__ h_in, const float* __restrict__ c_in,
    float* __restrict__ h_out, float* __restrict__ c_out,
    const int* __restrict__ p_lim, int s)
{
    const int x0 = (blockIdx.x * blockDim.x + threadIdx.x) * 4;
    const int y0 = blockIdx.y * blockDim.y + threadIdx.y;
    const bool hasL = x0 > 0, hasR = x0 + 4 < WW;
    const bool active = s < p_lim[0];

#pragma unroll
    for (int half = 0; half < 2; half++) {
        const int y = y0 + half * YSPLIT;
        const size_t base = (size_t)y * WW + x0;

        if (!active) {
            *(float4*)(h_out + base) = *(const float4*)(h_in + base);
            *(float4*)(c_out + base) = *(const float4*)(c_in + base);
            continue;
        }

        float hv[3][6];
        load_nbhd(h_in, y, x0, hasL, hasR, hv);

        float acc[4][4];
#pragma unroll
        for (int j = 0; j < 4; j++) {
            const float4 gv = g_gx[base + j];
            acc[j][0] = gv.x; acc[j][1] = gv.y; acc[j][2] = gv.z; acc[j][3] = gv.w;
        }

#pragma unroll
        for (int dy = 0; dy < 3; dy++)
#pragma unroll
            for (int dx = 0; dx < 3; dx++)
#pragma unroll
                for (int g = 0; g < 4; g++) {
                    const float wh = c_w[1][g * 18 + 9 + dy * 3 + dx];
#pragma unroll
                    for (int j = 0; j < 4; j++) acc[j][g] += wh * hv[dy][j + dx];
                }

        const float4 cc = *(const float4*)(c_in + base);
        const float cp[4] = {cc.x, cc.y, cc.z, cc.w};

        float hn[4], cn[4];
#pragma unroll
        for (int j = 0; j < 4; j++) {
            const float ig = fmaf(tanhx(acc[j][0]), 0.5f, 0.5f);
            const float fg = fmaf(tanhx(acc[j][1]), 0.5f, 0.5f);
            const float og = fmaf(tanhx(acc[j][2]), 0.5f, 0.5f);
            const float gg = tanhx(acc[j][3]);
            const float c2 = fmaf(fg, cp[j], ig * gg);
            cn[j] = c2;
            hn[j] = og * tanhx(c2);
        }
        *(float4*)(h_out + base) = make_float4(hn[0], hn[1], hn[2], hn[3]);
        *(float4*)(c_out + base) = make_float4(cn[0], cn[1], cn[2], cn[3]);
    }
}

extern "C" void kernel_launch(void* const* d_in, const int* in_sizes, int n_in,
                              void* d_out, int out_size)
{
    const float* data  = (const float*)d_in[0];   // [20,1,1,1024,1024]
    const float* enc_w = (const float*)d_in[1];
    const float* enc_b = (const float*)d_in[2];
    const float* dec_w = (const float*)d_in[3];
    const float* dec_b = (const float*)d_in[4];
    const int*   epoch = (const int*)d_in[5];
    const int*   t_en  = (const int*)d_in[6];
    const int*   t_de  = (const int*)d_in[7];
    float*       out   = (float*)d_out;           // [1024,1024]

    // Prescaled weights -> constant bank (all graph-legal nodes).
    prep_kernel<<<1, 160>>>(enc_w, enc_b, dec_w, dec_b);
    void *wp = nullptr, *bp = nullptr;
    cudaGetSymbolAddress(&wp, g_wpack);
    cudaGetSymbolAddress(&bp, g_bpack);
    cudaMemcpyToSymbolAsync(c_w, wp, sizeof(float) * 2 * 72, 0,
                            cudaMemcpyDeviceToDevice, 0);
    cudaMemcpyToSymbolAsync(c_b, bp, sizeof(float) * 2 * 4, 0,
                            cudaMemcpyDeviceToDevice, 0);

    float *hbuf = nullptr, *cbuf = nullptr, *xdec = nullptr;
    cudaGetSymbolAddress((void**)&hbuf, g_h);
    cudaGetSymbolAddress((void**)&cbuf, g_c);
    cudaGetSymbolAddress((void**)&xdec, g_x);
    float* hA = hbuf;  float* hB = hbuf + HWSZ;
    float* cA = cbuf;  float* cB = cbuf + HWSZ;

    const dim3 blk(64, 4);
    const dim3 grd(WW / 256, YSPLIT / 4);   // (4, 128) = 512 blocks -> single wave

    // ---- Encoder: 20 launches, active while epoch+s < T_en ----
    enc_step<true><<<grd, blk>>>(data, hA, cA, hB, cB, epoch, t_en, 0);
    for (int s = 1; s < 20; s++) {
        float* hi = (s & 1) ? hB : hA;
        float* ho = (s & 1) ? hA : hB;
        float* ci = (s & 1) ? cB : cA;
        float* co = (s & 1) ? cA : cB;
        enc_step<false><<<grd, blk>>>(data, hi, ci, ho, co, epoch, t_en, s);
    }
    // Final encoder h in hA (untouched below) = decoder's constant input x.

    // ---- Precompute decoder x-gates once ----
    gx_kernel<<<grd, blk>>>(hA);

    // ---- Decoder: step 0 pointwise, then 19 h-only conv steps ----
    dec_first<<<grd, blk>>>(xdec, cA, t_de);
    for (int s = 1; s < 20; s++) {
        float* hi = (s & 1) ? xdec : out;
        float* ho = (s & 1) ? out  : xdec;
        float* ci = (s & 1) ? cA : cB;
        float* co = (s & 1) ? cB : cA;
        dec_step<<<grd, blk>>>(hi, ci, ho, co, t_de, s);
    }
    // s=19 (odd) wrote h into d_out directly.
}